// round 15
// baseline (speedup 1.0000x reference)
#include <cuda_runtime.h>
#include <cuda_bf16.h>
#include <cstdint>
#include <cstddef>
#include <math.h>

// Dims
#define Bn 32
#define Sn 128
#define Pn 32
#define In 512
#define Hn 512
#define G3 1536
#define On 10

// Output layout: out[32,10] | states[32,128,512] | context[32,512] | alpha[32,128]
#define OFF_OUT 0
#define OFF_ST  320
#define OFF_CTX 2097472
#define OFF_AL  2113856

// -------- scratch (__device__ globals; no allocations allowed) --------------
__device__ float g_conv[Sn*Bn*In];
__device__ float g_emb [Sn*Bn*In];
__device__ float g_gi0 [Sn*Bn*G3];
__device__ float g_st0 [Sn*Bn*Hn];
__device__ float g_gi1 [Sn*Bn*G3];
__device__ float g_hT2[2*Hn*Bn];     // double-buffered h, transposed [j][b]
// per-CTA step flags, each on its own 128B line. Two arrays (one per layer);
// each layer resets the OTHER layer's array (stream-ordered, race-free).
__device__ __align__(128) unsigned g_flagA[128*32];
__device__ __align__(128) unsigned g_flagB[128*32];

// -------- helpers -----------------------------------------------------------
__device__ __forceinline__ float wred(float v) {
    #pragma unroll
    for (int o = 16; o; o >>= 1) v += __shfl_xor_sync(0xffffffffu, v, o);
    return v;
}
__device__ __forceinline__ unsigned ld_acq(const unsigned* p) {
    unsigned v;
    asm volatile("ld.acquire.gpu.u32 %0,[%1];" : "=r"(v) : "l"(p) : "memory");
    return v;
}
__device__ __forceinline__ void st_rel(unsigned* p, unsigned v) {
    asm volatile("st.release.gpu.u32 [%0],%1;" :: "l"(p), "r"(v) : "memory");
}
__device__ __forceinline__ float ldcg(const float* p) {
    float v;
    asm volatile("ld.global.cg.f32 %0,[%1];" : "=f"(v) : "l"(p));
    return v;
}
// fast overflow-safe sigmoid / tanh (rel err ~1e-6; margin vs 1e-3 is huge)
__device__ __forceinline__ float sigf(float x) {
    return __fdividef(1.f, 1.f + __expf(-x));
}
__device__ __forceinline__ float tanhfast(float x) {
    float t = __expf(-2.f * fabsf(x));
    float r = __fdividef(1.f - t, 1.f + t);
    return copysignf(r, x);
}
#define FMA2(d,a,b) asm("fma.rn.f32x2 %0,%1,%2,%0;" : "+l"(d) : "l"(a), "l"(b))
#define BCAST2(d,f) asm("mov.b64 %0,{%1,%1};" : "=l"(d) : "f"(f))
#define PACK2(d,x,y) asm("mov.b64 %0,{%1,%2};" : "=l"(d) : "f"(x), "f"(y))
#define UNPK2(x,y,d) asm("mov.b64 {%0,%1},%2;" : "=f"(x), "=f"(y) : "l"(d))

// ======== K1: conv-attention pooling over P (conv_b cancels in softmax) =====
__global__ __launch_bounds__(256)
void conv_pool_kernel(const float* __restrict__ in, const float* __restrict__ conv_w,
                      float* __restrict__ conv_all) {
    __shared__ float cw[In];
    __shared__ float sc[Pn];
    __shared__ float at[Pn];
    const int tid = threadIdx.x;
    const int bx = blockIdx.x;          // b*S + s
    const int b = bx >> 7, s = bx & 127;
    const float* base = in + (size_t)bx * (Pn * In);

    if (tid < 128) ((float4*)cw)[tid] = ((const float4*)conv_w)[tid];
    __syncthreads();

    const int w = tid >> 5, lane = tid & 31;
    #pragma unroll
    for (int q = 0; q < 4; q++) {
        int p = w * 4 + q;
        const float4* row = (const float4*)(base + (size_t)p * In);
        const float4* cw4 = (const float4*)cw;
        float acc = 0.f;
        for (int kk = lane; kk < 128; kk += 32) {
            float4 x = row[kk], y = cw4[kk];
            acc += x.x*y.x + x.y*y.y + x.z*y.z + x.w*y.w;
        }
        acc = wred(acc);
        if (lane == 0) sc[p] = acc;
    }
    __syncthreads();

    if (tid < 32) {
        float v = sc[tid], m = v;
        #pragma unroll
        for (int o = 16; o; o >>= 1) m = fmaxf(m, __shfl_xor_sync(0xffffffffu, m, o));
        float e = expf(v - m);
        float ssum = wred(e);
        at[tid] = e / ssum;
    }
    __syncthreads();

    float* dst = conv_all + ((size_t)s * Bn + b) * In;   // row = s*32+b
    for (int i = tid; i < In; i += 256) {
        float acc = 0.f;
        #pragma unroll 8
        for (int p = 0; p < Pn; p++) acc += at[p] * base[(size_t)p * In + i];
        dst[i] = acc;
    }
}

// ======== GEMM  C[M,N] = act(A[M,512] @ W[N,512]^T + bias) ==================
// Software-pipelined k-tiles (neutral vs R12, kept).
#define GBM 128
#define GBN 64
#define GBK 32
__global__ __launch_bounds__(256)
void gemm_tn(const float* __restrict__ A, const float* __restrict__ W,
             const float* __restrict__ bias, float* __restrict__ C,
             int N, int act) {
    __shared__ float As[GBK][GBM + 4];
    __shared__ float Ws[GBK][GBN + 4];
    const int tid = threadIdx.x;
    const int row0 = blockIdx.y * GBM;
    const int col0 = blockIdx.x * GBN;
    const int m0 = (tid >> 4) * 8;      // 0..120
    const int n0 = (tid & 15) * 4;      // 0..60
    unsigned long long acc[8][2];
    #pragma unroll
    for (int i = 0; i < 8; i++) { acc[i][0] = 0ULL; acc[i][1] = 0ULL; }

    const int am[4] = {tid & 127, (tid + 256) & 127, (tid + 512) & 127, (tid + 768) & 127};
    const int ak[4] = {tid >> 7, (tid + 256) >> 7, (tid + 512) >> 7, (tid + 768) >> 7};
    const int wn[2] = {tid & 63, (tid + 256) & 63};
    const int wk[2] = {tid >> 6, (tid + 256) >> 6};

    float4 Ar[4], Wr[2];
    #pragma unroll
    for (int l = 0; l < 4; l++)
        Ar[l] = *(const float4*)(A + (size_t)(row0 + am[l]) * 512 + ak[l] * 4);
    #pragma unroll
    for (int l = 0; l < 2; l++)
        Wr[l] = *(const float4*)(W + (size_t)(col0 + wn[l]) * 512 + wk[l] * 4);

    for (int k0 = 0; k0 < 512; k0 += GBK) {
        #pragma unroll
        for (int l = 0; l < 4; l++) {
            int m = am[l], kq = ak[l];
            As[kq*4+0][m] = Ar[l].x; As[kq*4+1][m] = Ar[l].y;
            As[kq*4+2][m] = Ar[l].z; As[kq*4+3][m] = Ar[l].w;
        }
        #pragma unroll
        for (int l = 0; l < 2; l++) {
            int n = wn[l], kq = wk[l];
            Ws[kq*4+0][n] = Wr[l].x; Ws[kq*4+1][n] = Wr[l].y;
            Ws[kq*4+2][n] = Wr[l].z; Ws[kq*4+3][n] = Wr[l].w;
        }
        __syncthreads();

        if (k0 + GBK < 512) {
            #pragma unroll
            for (int l = 0; l < 4; l++)
                Ar[l] = *(const float4*)(A + (size_t)(row0 + am[l]) * 512 + k0 + GBK + ak[l] * 4);
            #pragma unroll
            for (int l = 0; l < 2; l++)
                Wr[l] = *(const float4*)(W + (size_t)(col0 + wn[l]) * 512 + k0 + GBK + wk[l] * 4);
        }

        #pragma unroll
        for (int k = 0; k < GBK; k++) {
            float4 a0 = *(const float4*)&As[k][m0];
            float4 a1 = *(const float4*)&As[k][m0 + 4];
            float4 wv = *(const float4*)&Ws[k][n0];
            unsigned long long w01, w23;
            PACK2(w01, wv.x, wv.y);
            PACK2(w23, wv.z, wv.w);
            float amr[8] = {a0.x,a0.y,a0.z,a0.w,a1.x,a1.y,a1.z,a1.w};
            #pragma unroll
            for (int i = 0; i < 8; i++) {
                unsigned long long ai;
                BCAST2(ai, amr[i]);
                FMA2(acc[i][0], ai, w01);
                FMA2(acc[i][1], ai, w23);
            }
        }
        __syncthreads();
    }
    float bv0 = 0.f, bv1 = 0.f, bv2 = 0.f, bv3 = 0.f;
    if (bias) {
        bv0 = bias[col0+n0]; bv1 = bias[col0+n0+1];
        bv2 = bias[col0+n0+2]; bv3 = bias[col0+n0+3];
    }
    #pragma unroll
    for (int i = 0; i < 8; i++) {
        float c0, c1, c2, c3;
        UNPK2(c0, c1, acc[i][0]);
        UNPK2(c2, c3, acc[i][1]);
        float4 o = {c0 + bv0, c1 + bv1, c2 + bv2, c3 + bv3};
        if (act == 1) {
            o.x = fminf(1.f, fmaxf(-1.f, o.x));
            o.y = fminf(1.f, fmaxf(-1.f, o.y));
            o.z = fminf(1.f, fmaxf(-1.f, o.z));
            o.w = fminf(1.f, fmaxf(-1.f, o.w));
        }
        *(float4*)(C + (size_t)(row0 + m0 + i) * N + col0 + n0) = o;
    }
}

// ======== GRU persistent recurrence (R12 + early publish, 1 syncthreads) ====
// grid=128 CTAs, 1024 thr (32 warps). CTA c owns h-columns [4c,4c+4).
// Warp w: lane=b, 16-k slice k0 = q*128 + (w&7)*16, q=((w>>3)+cta)&3;
// polls its slice's 4 producer flags. red double-buffered by step parity so
// only ONE CTA-wide __syncthreads per step (between dot-write and gate-read).
// Gate warps (0-3) order h-stores with bar.sync(3,128); tid0 publishes the
// flag immediately after — dot warps never wait on the gate phase.
#define SM_WP   0
#define RED_HALF_F 13312                  /* floats per red half (32*32*13) */
#define SM_RED  32768
#define SM_BH   (32768 + 2*RED_HALF_F*4)
#define GRU_SMEM (SM_BH + 64)

__global__ __launch_bounds__(1024)
void gru_kernel(const float* __restrict__ gi, const float* __restrict__ Whh,
                const float* __restrict__ bhh, float* __restrict__ st_out,
                int lay1) {
    extern __shared__ char sm[];
    float* wp  = (float*)(sm + SM_WP);    // [k][16] floats; cols c=0..11 (c=g*4+jl)
    float* red = (float*)(sm + SM_RED);   // 2 x [(w*32+b)*13 + c]
    float* bh  = (float*)(sm + SM_BH);    // [12]
    const int tid = threadIdx.x;
    const int cta = blockIdx.x;

    unsigned* flg = lay1 ? g_flagB : g_flagA;
    // reset the OTHER layer's flag (only touched by the previous launch)
    if (tid == 0) (lay1 ? g_flagA : g_flagB)[cta * 32] = 0;

    // weights: wp[k*16 + c] = Whh[(g*512 + cta*4 + jl)*512 + k], c = g*4+jl
    for (int i = tid; i < 6144; i += 1024) {
        int c = i >> 9, k = i & 511;
        int g = c >> 2, jl = c & 3;
        wp[k * 16 + c] = Whh[(size_t)(g * 512 + cta * 4 + jl) * 512 + k];
    }
    if (tid < 12) bh[tid] = bhh[(tid >> 2) * 512 + cta * 4 + (tid & 3)];
    __syncthreads();

    const int lane = tid & 31, w = tid >> 5;
    const int q = ((w >> 3) + cta) & 3;          // chunk this warp consumes
    const int k0 = q * 128 + (w & 7) * 16;       // warp's 16-k slice
    const int pc0 = k0 >> 2;                     // first producer CTA of slice
    const unsigned* myflag = &flg[(pc0 + (lane & 3)) * 32];
    // gate-phase identity (tid < 128)
    const int bb = tid & 31, jl = (tid >> 5) & 3;
    const int jg = cta * 4 + jl;

    float giv0 = 0.f, giv1 = 0.f, giv2 = 0.f, ho = 0.f;
    if (tid < 128) {
        giv0 = __ldg(gi + (size_t)bb * G3 + jg);
        giv1 = __ldg(gi + (size_t)bb * G3 + 512 + jg);
        giv2 = __ldg(gi + (size_t)bb * G3 + 1024 + jg);
    }

    for (int s = 0; s < 128; s++) {
        float* rbuf = red + (s & 1) * RED_HALF_F;
        if (s > 0) {
            // ---- warp-autonomous wait for THIS slice's 4 producers ----
            {
                unsigned tgt = (unsigned)s;
                while (!__all_sync(0xffffffffu, ld_acq(myflag) >= tgt)) { }
            }

            // ---- direct L2 read (cg): all 16 h loads in flight at once ----
            const float* hb = g_hT2 + ((s + 1) & 1) * (Hn * Bn) + (size_t)k0 * 32 + lane;
            float hr[16];
            #pragma unroll
            for (int i = 0; i < 16; i++) hr[i] = ldcg(hb + i * 32);

            unsigned long long acc[6];
            #pragma unroll
            for (int p = 0; p < 6; p++) acc[p] = 0ULL;
            #pragma unroll
            for (int i = 0; i < 16; i++) {
                unsigned long long h2;
                BCAST2(h2, hr[i]);
                const ulonglong2* wk = (const ulonglong2*)(wp + (k0 + i) * 16);
                ulonglong2 A = wk[0], Bv = wk[1], Cv = wk[2];
                FMA2(acc[0], h2, A.x);  FMA2(acc[1], h2, A.y);
                FMA2(acc[2], h2, Bv.x); FMA2(acc[3], h2, Bv.y);
                FMA2(acc[4], h2, Cv.x); FMA2(acc[5], h2, Cv.y);
            }
            float* rr = rbuf + (w * 32 + lane) * 13;
            #pragma unroll
            for (int p = 0; p < 6; p++) {
                float x, y;
                UNPK2(x, y, acc[p]);
                rr[2 * p] = x; rr[2 * p + 1] = y;
            }
        }
        // single CTA-wide barrier per step: orders red writes (this step) and
        // red-half reuse (2 steps apart) against the gate phase.
        __syncthreads();

        // ---- gate phase: warps 0-3 only; dot warps proceed to next poll ----
        if (tid < 128) {
            float gh0 = 0.f, gh1 = 0.f, gh2 = 0.f;
            if (s > 0) {
                #pragma unroll
                for (int ww = 0; ww < 32; ww++) {
                    const float* rr = rbuf + (ww * 32 + bb) * 13;
                    gh0 += rr[jl];
                    gh1 += rr[4 + jl];
                    gh2 += rr[8 + jl];
                }
            }
            float r = sigf(giv0 + gh0 + bh[jl]);
            float z = sigf(giv1 + gh1 + bh[4 + jl]);
            float nn = tanhfast(giv2 + r * (gh2 + bh[8 + jl]));
            float hn = (1.f - z) * nn + z * ho;
            ho = hn;
            g_hT2[(s & 1) * (Hn * Bn) + jg * 32 + bb] = hn;
            // order the 4 gate warps' h stores, then publish immediately
            asm volatile("bar.sync 3, 128;" ::: "memory");
            if (tid == 0) st_rel(&flg[cta * 32], (unsigned)(s + 1));
            // off-critical-path: states write + next gi prefetch
            size_t oidx = lay1 ? ((size_t)bb * 128 + s) * 512 + jg
                               : ((size_t)s * 32 + bb) * 512 + jg;
            st_out[oidx] = hn;
            if (s < 127) {
                size_t gib = ((size_t)(s + 1) * 32 + bb) * (size_t)G3;
                giv0 = __ldg(gi + gib + jg);
                giv1 = __ldg(gi + gib + 512 + jg);
                giv2 = __ldg(gi + gib + 1024 + jg);
            }
        }
    }
}

// ======== final: time-attention + linear + softmax ==========================
// states layout here: [b][s][h] (written directly by layer-1 GRU into d_out)
__global__ __launch_bounds__(256)
void final_kernel(const float* __restrict__ states, const float* __restrict__ attw,
                  const float* __restrict__ demoip, const float* __restrict__ linW,
                  const float* __restrict__ linb, float* __restrict__ out) {
    __shared__ float aw[512];
    __shared__ float lg[128];
    __shared__ float al[128];
    __shared__ float ctx[512];
    __shared__ float o10[10];
    const int tid = threadIdx.x, b = blockIdx.x;
    const int w = tid >> 5, lane = tid & 31;
    const float* stb = states + (size_t)b * 128 * 512;

    for (int h = tid; h < 512; h += 256) aw[h] = attw[h];
    __syncthreads();

    for (int s = w; s < 128; s += 8) {
        const float* row = stb + (size_t)s * 512;
        float acc = 0.f;
        for (int h = lane; h < 512; h += 32) acc += row[h] * aw[h];
        acc = wred(acc);
        if (lane == 0) lg[s] = acc;
    }
    __syncthreads();

    if (tid < 32) {
        float v[4]; float m = -1e30f;
        #pragma unroll
        for (int q = 0; q < 4; q++) { v[q] = lg[tid + q * 32]; m = fmaxf(m, v[q]); }
        #pragma unroll
        for (int o = 16; o; o >>= 1) m = fmaxf(m, __shfl_xor_sync(0xffffffffu, m, o));
        float ssum = 0.f;
        #pragma unroll
        for (int q = 0; q < 4; q++) { v[q] = expf(v[q] - m); ssum += v[q]; }
        ssum = wred(ssum);
        #pragma unroll
        for (int q = 0; q < 4; q++) {
            float a = v[q] / ssum;
            al[tid + q * 32] = a;
            out[OFF_AL + b * 128 + tid + q * 32] = a;
        }
    }
    __syncthreads();

    for (int h = tid; h < 512; h += 256) {
        float acc = 0.f;
        for (int s = 0; s < 128; s++) acc += al[s] * stb[(size_t)s * 512 + h];
        ctx[h] = acc;
        out[OFF_CTX + b * 512 + h] = acc;
    }
    __syncthreads();

    if (tid < 10) {
        float acc = linb[tid];
        const float* wrow = linW + tid * 515;
        for (int h = 0; h < 512; h++) acc += ctx[h] * wrow[h];
        for (int d = 0; d < 3; d++) acc += demoip[b * 3 + d] * wrow[512 + d];
        o10[tid] = acc;
    }
    __syncthreads();
    if (tid < 10) {
        float m = -1e30f;
        for (int o = 0; o < 10; o++) m = fmaxf(m, o10[o]);
        float e = expf(o10[tid] - m), ssum = 0.f;
        for (int o = 0; o < 10; o++) ssum += expf(o10[o] - m);
        out[OFF_OUT + b * 10 + tid] = e / ssum;
    }
}

// ======== launch ============================================================
extern "C" void kernel_launch(void* const* d_in, const int* in_sizes, int n_in,
                              void* d_out, int out_size) {
    // batch_size may or may not be materialized as input[2] (size-1 scalar).
    int sh = (in_sizes[2] == 1) ? 1 : 0;

    const float* inp   = (const float*)d_in[0];
    const float* demo  = (const float*)d_in[1];
    const float* convw = (const float*)d_in[2 + sh];
    // conv_b at [3+sh] cancels in the softmax; unused.
    const float* embW  = (const float*)d_in[4 + sh];
    const float* Wi0   = (const float*)d_in[5 + sh];
    const float* Wh0   = (const float*)d_in[6 + sh];
    const float* bi0   = (const float*)d_in[7 + sh];
    const float* bh0   = (const float*)d_in[8 + sh];
    const float* Wi1   = (const float*)d_in[9 + sh];
    const float* Wh1   = (const float*)d_in[10 + sh];
    const float* bi1   = (const float*)d_in[11 + sh];
    const float* bh1   = (const float*)d_in[12 + sh];
    const float* attw  = (const float*)d_in[13 + sh];
    const float* linW  = (const float*)d_in[14 + sh];
    const float* linb  = (const float*)d_in[15 + sh];
    float* out = (float*)d_out;

    cudaFuncSetAttribute(gru_kernel, cudaFuncAttributeMaxDynamicSharedMemorySize, GRU_SMEM);

    void *pc, *pe, *p0, *ps0, *p1;
    cudaGetSymbolAddress(&pc, g_conv);
    cudaGetSymbolAddress(&pe, g_emb);
    cudaGetSymbolAddress(&p0, g_gi0);
    cudaGetSymbolAddress(&ps0, g_st0);
    cudaGetSymbolAddress(&p1, g_gi1);

    conv_pool_kernel<<<Bn * Sn, 256>>>(inp, convw, (float*)pc);

    dim3 ge(In / GBN, (Sn * Bn) / GBM);   // (8, 32)
    dim3 gg(G3 / GBN, (Sn * Bn) / GBM);   // (24, 32)
    gemm_tn<<<ge, 256>>>((const float*)pc, embW, nullptr, (float*)pe, In, 1);
    gemm_tn<<<gg, 256>>>((const float*)pe, Wi0, bi0, (float*)p0, G3, 0);

    gru_kernel<<<128, 1024, GRU_SMEM>>>((const float*)p0, Wh0, bh0, (float*)ps0, 0);

    gemm_tn<<<gg, 256>>>((const float*)ps0, Wi1, bi1, (float*)p1, G3, 0);

    gru_kernel<<<128, 1024, GRU_SMEM>>>((const float*)p1, Wh1, bh1, out + OFF_ST, 1);

    final_kernel<<<Bn, 256>>>(out + OFF_ST, attw, demo, linW, linb, out);
}

// round 16
// speedup vs baseline: 1.0180x; 1.0180x over previous
#include <cuda_runtime.h>
#include <cuda_bf16.h>
#include <cstdint>
#include <cstddef>
#include <math.h>

// Dims
#define Bn 32
#define Sn 128
#define Pn 32
#define In 512
#define Hn 512
#define G3 1536
#define On 10

// Output layout: out[32,10] | states[32,128,512] | context[32,512] | alpha[32,128]
#define OFF_OUT 0
#define OFF_ST  320
#define OFF_CTX 2097472
#define OFF_AL  2113856

// -------- scratch (__device__ globals; no allocations allowed) --------------
__device__ float g_conv[Sn*Bn*In];
__device__ float g_emb [Sn*Bn*In];
__device__ float g_gi0 [Sn*Bn*G3];
__device__ float g_st0 [Sn*Bn*Hn];
__device__ float g_gi1 [Sn*Bn*G3];
__device__ float g_hT2[2*Hn*Bn];     // double-buffered h, transposed [j][b]
// per-CTA step flags, each on its own 128B line. Two arrays (one per layer);
// each layer resets the OTHER layer's array (stream-ordered, race-free).
__device__ __align__(128) unsigned g_flagA[128*32];
__device__ __align__(128) unsigned g_flagB[128*32];

// -------- helpers -----------------------------------------------------------
__device__ __forceinline__ float wred(float v) {
    #pragma unroll
    for (int o = 16; o; o >>= 1) v += __shfl_xor_sync(0xffffffffu, v, o);
    return v;
}
__device__ __forceinline__ unsigned ld_acq(const unsigned* p) {
    unsigned v;
    asm volatile("ld.acquire.gpu.u32 %0,[%1];" : "=r"(v) : "l"(p) : "memory");
    return v;
}
__device__ __forceinline__ void st_rel(unsigned* p, unsigned v) {
    asm volatile("st.release.gpu.u32 [%0],%1;" :: "l"(p), "r"(v) : "memory");
}
__device__ __forceinline__ float ldcg(const float* p) {
    float v;
    asm volatile("ld.global.cg.f32 %0,[%1];" : "=f"(v) : "l"(p));
    return v;
}
#define FMA2(d,a,b) asm("fma.rn.f32x2 %0,%1,%2,%0;" : "+l"(d) : "l"(a), "l"(b))
#define BCAST2(d,f) asm("mov.b64 %0,{%1,%1};" : "=l"(d) : "f"(f))
#define PACK2(d,x,y) asm("mov.b64 %0,{%1,%2};" : "=l"(d) : "f"(x), "f"(y))
#define UNPK2(x,y,d) asm("mov.b64 {%0,%1},%2;" : "=f"(x), "=f"(y) : "l"(d))

// ======== K1: conv-attention pooling over P — single DRAM pass via smem ====
// Tile (32x512 f32 = 64KB) staged in dynamic smem; scores, softmax and
// pooling all read smem. conv_b cancels in the softmax.
#define CONV_SMEM (Pn * In * 4)
__global__ __launch_bounds__(256)
void conv_pool_kernel(const float* __restrict__ in, const float* __restrict__ conv_w,
                      float* __restrict__ conv_all) {
    extern __shared__ float tile[];     // [p][i] 32 x 512
    __shared__ float cw[In];
    __shared__ float sc[Pn];
    __shared__ float at[Pn];
    const int tid = threadIdx.x;
    const int bx = blockIdx.x;          // b*S + s
    const int b = bx >> 7, s = bx & 127;
    const float* base = in + (size_t)bx * (Pn * In);

    // stage tile: 4096 float4 by 256 threads (16 each)
    {
        const float4* src = (const float4*)base;
        float4* dst4 = (float4*)tile;
        #pragma unroll
        for (int l = 0; l < 16; l++) dst4[tid + l * 256] = src[tid + l * 256];
    }
    if (tid < 128) ((float4*)cw)[tid] = ((const float4*)conv_w)[tid];
    __syncthreads();

    const int w = tid >> 5, lane = tid & 31;
    #pragma unroll
    for (int q = 0; q < 4; q++) {
        int p = w * 4 + q;
        const float4* row = (const float4*)(tile + (size_t)p * In);
        const float4* cw4 = (const float4*)cw;
        float acc = 0.f;
        for (int kk = lane; kk < 128; kk += 32) {
            float4 x = row[kk], y = cw4[kk];
            acc += x.x*y.x + x.y*y.y + x.z*y.z + x.w*y.w;
        }
        acc = wred(acc);
        if (lane == 0) sc[p] = acc;
    }
    __syncthreads();

    if (tid < 32) {
        float v = sc[tid], m = v;
        #pragma unroll
        for (int o = 16; o; o >>= 1) m = fmaxf(m, __shfl_xor_sync(0xffffffffu, m, o));
        float e = expf(v - m);
        float ssum = wred(e);
        at[tid] = e / ssum;
    }
    __syncthreads();

    float* dst = conv_all + ((size_t)s * Bn + b) * In;   // row = s*32+b
    for (int i = tid; i < In; i += 256) {
        float acc = 0.f;
        #pragma unroll 8
        for (int p = 0; p < Pn; p++) acc += at[p] * tile[(size_t)p * In + i];
        dst[i] = acc;
    }
}

// ======== GEMM  C[M,N] = act(A[M,512] @ W[N,512]^T + bias) ==================
// Software-pipelined k-tiles.
#define GBM 128
#define GBN 64
#define GBK 32
__global__ __launch_bounds__(256)
void gemm_tn(const float* __restrict__ A, const float* __restrict__ W,
             const float* __restrict__ bias, float* __restrict__ C,
             int N, int act) {
    __shared__ float As[GBK][GBM + 4];
    __shared__ float Ws[GBK][GBN + 4];
    const int tid = threadIdx.x;
    const int row0 = blockIdx.y * GBM;
    const int col0 = blockIdx.x * GBN;
    const int m0 = (tid >> 4) * 8;      // 0..120
    const int n0 = (tid & 15) * 4;      // 0..60
    unsigned long long acc[8][2];
    #pragma unroll
    for (int i = 0; i < 8; i++) { acc[i][0] = 0ULL; acc[i][1] = 0ULL; }

    const int am[4] = {tid & 127, (tid + 256) & 127, (tid + 512) & 127, (tid + 768) & 127};
    const int ak[4] = {tid >> 7, (tid + 256) >> 7, (tid + 512) >> 7, (tid + 768) >> 7};
    const int wn[2] = {tid & 63, (tid + 256) & 63};
    const int wk[2] = {tid >> 6, (tid + 256) >> 6};

    float4 Ar[4], Wr[2];
    #pragma unroll
    for (int l = 0; l < 4; l++)
        Ar[l] = *(const float4*)(A + (size_t)(row0 + am[l]) * 512 + ak[l] * 4);
    #pragma unroll
    for (int l = 0; l < 2; l++)
        Wr[l] = *(const float4*)(W + (size_t)(col0 + wn[l]) * 512 + wk[l] * 4);

    for (int k0 = 0; k0 < 512; k0 += GBK) {
        #pragma unroll
        for (int l = 0; l < 4; l++) {
            int m = am[l], kq = ak[l];
            As[kq*4+0][m] = Ar[l].x; As[kq*4+1][m] = Ar[l].y;
            As[kq*4+2][m] = Ar[l].z; As[kq*4+3][m] = Ar[l].w;
        }
        #pragma unroll
        for (int l = 0; l < 2; l++) {
            int n = wn[l], kq = wk[l];
            Ws[kq*4+0][n] = Wr[l].x; Ws[kq*4+1][n] = Wr[l].y;
            Ws[kq*4+2][n] = Wr[l].z; Ws[kq*4+3][n] = Wr[l].w;
        }
        __syncthreads();

        if (k0 + GBK < 512) {
            #pragma unroll
            for (int l = 0; l < 4; l++)
                Ar[l] = *(const float4*)(A + (size_t)(row0 + am[l]) * 512 + k0 + GBK + ak[l] * 4);
            #pragma unroll
            for (int l = 0; l < 2; l++)
                Wr[l] = *(const float4*)(W + (size_t)(col0 + wn[l]) * 512 + k0 + GBK + wk[l] * 4);
        }

        #pragma unroll
        for (int k = 0; k < GBK; k++) {
            float4 a0 = *(const float4*)&As[k][m0];
            float4 a1 = *(const float4*)&As[k][m0 + 4];
            float4 wv = *(const float4*)&Ws[k][n0];
            unsigned long long w01, w23;
            PACK2(w01, wv.x, wv.y);
            PACK2(w23, wv.z, wv.w);
            float amr[8] = {a0.x,a0.y,a0.z,a0.w,a1.x,a1.y,a1.z,a1.w};
            #pragma unroll
            for (int i = 0; i < 8; i++) {
                unsigned long long ai;
                BCAST2(ai, amr[i]);
                FMA2(acc[i][0], ai, w01);
                FMA2(acc[i][1], ai, w23);
            }
        }
        __syncthreads();
    }
    float bv0 = 0.f, bv1 = 0.f, bv2 = 0.f, bv3 = 0.f;
    if (bias) {
        bv0 = bias[col0+n0]; bv1 = bias[col0+n0+1];
        bv2 = bias[col0+n0+2]; bv3 = bias[col0+n0+3];
    }
    #pragma unroll
    for (int i = 0; i < 8; i++) {
        float c0, c1, c2, c3;
        UNPK2(c0, c1, acc[i][0]);
        UNPK2(c2, c3, acc[i][1]);
        float4 o = {c0 + bv0, c1 + bv1, c2 + bv2, c3 + bv3};
        if (act == 1) {
            o.x = fminf(1.f, fmaxf(-1.f, o.x));
            o.y = fminf(1.f, fmaxf(-1.f, o.y));
            o.z = fminf(1.f, fmaxf(-1.f, o.z));
            o.w = fminf(1.f, fmaxf(-1.f, o.w));
        }
        *(float4*)(C + (size_t)(row0 + m0 + i) * N + col0 + n0) = o;
    }
}

// ======== GRU persistent recurrence (R12: best measured structure) ==========
// grid=128 CTAs, 1024 thr (32 warps, 8/SMSP for latency hiding).
// CTA c owns h-columns [4c,4c+4) (12 gate cols).
// Warp w: lane=b, 16-k slice k0 = q*128 + (w&7)*16, q=((w>>3)+cta)&3.
// Slice spans 4 producer CTAs -> warp polls 4 per-CTA flags (lane&3).
// h read via ld.global.cg (coherent, MLP=16). Flags: single writer st.release.
#define SM_WP   0
#define SM_RED  32768
#define SM_BH   (32768 + 53248)
#define GRU_SMEM (32768 + 53248 + 64)

__global__ __launch_bounds__(1024)
void gru_kernel(const float* __restrict__ gi, const float* __restrict__ Whh,
                const float* __restrict__ bhh, float* __restrict__ st_out,
                int lay1) {
    extern __shared__ char sm[];
    float* wp  = (float*)(sm + SM_WP);    // [k][16] floats; cols c=0..11 (c=g*4+jl)
    float* red = (float*)(sm + SM_RED);   // [(w*32+b)*13 + c], 32 warps
    float* bh  = (float*)(sm + SM_BH);    // [12]
    const int tid = threadIdx.x;
    const int cta = blockIdx.x;

    unsigned* flg = lay1 ? g_flagB : g_flagA;
    // reset the OTHER layer's flag (only touched by the previous launch)
    if (tid == 0) (lay1 ? g_flagA : g_flagB)[cta * 32] = 0;

    // weights: wp[k*16 + c] = Whh[(g*512 + cta*4 + jl)*512 + k], c = g*4+jl
    for (int i = tid; i < 6144; i += 1024) {
        int c = i >> 9, k = i & 511;
        int g = c >> 2, jl = c & 3;
        wp[k * 16 + c] = Whh[(size_t)(g * 512 + cta * 4 + jl) * 512 + k];
    }
    if (tid < 12) bh[tid] = bhh[(tid >> 2) * 512 + cta * 4 + (tid & 3)];
    __syncthreads();

    const int lane = tid & 31, w = tid >> 5;
    const int q = ((w >> 3) + cta) & 3;          // chunk this warp consumes
    const int k0 = q * 128 + (w & 7) * 16;       // warp's 16-k slice
    const int pc0 = k0 >> 2;                     // first producer CTA of slice
    const unsigned* myflag = &flg[(pc0 + (lane & 3)) * 32];
    // gate-phase identity (tid < 128)
    const int bb = tid & 31, jl = (tid >> 5) & 3;
    const int jg = cta * 4 + jl;

    float giv0 = 0.f, giv1 = 0.f, giv2 = 0.f, ho = 0.f;
    if (tid < 128) {
        giv0 = __ldg(gi + (size_t)bb * G3 + jg);
        giv1 = __ldg(gi + (size_t)bb * G3 + 512 + jg);
        giv2 = __ldg(gi + (size_t)bb * G3 + 1024 + jg);
    }

    for (int s = 0; s < 128; s++) {
        if (s > 0) {
            // ---- warp-autonomous wait for THIS slice's 4 producers ----
            {
                unsigned tgt = (unsigned)s;
                while (!__all_sync(0xffffffffu, ld_acq(myflag) >= tgt)) { }
            }

            // ---- direct L2 read (cg): all 16 h loads in flight at once ----
            const float* hb = g_hT2 + ((s + 1) & 1) * (Hn * Bn) + (size_t)k0 * 32 + lane;
            float hr[16];
            #pragma unroll
            for (int i = 0; i < 16; i++) hr[i] = ldcg(hb + i * 32);

            unsigned long long acc[6];
            #pragma unroll
            for (int p = 0; p < 6; p++) acc[p] = 0ULL;
            #pragma unroll
            for (int i = 0; i < 16; i++) {
                unsigned long long h2;
                BCAST2(h2, hr[i]);
                const ulonglong2* wk = (const ulonglong2*)(wp + (k0 + i) * 16);
                ulonglong2 A = wk[0], Bv = wk[1], Cv = wk[2];
                FMA2(acc[0], h2, A.x);  FMA2(acc[1], h2, A.y);
                FMA2(acc[2], h2, Bv.x); FMA2(acc[3], h2, Bv.y);
                FMA2(acc[4], h2, Cv.x); FMA2(acc[5], h2, Cv.y);
            }
            float* rr = red + (w * 32 + lane) * 13;
            #pragma unroll
            for (int p = 0; p < 6; p++) {
                float x, y;
                UNPK2(x, y, acc[p]);
                rr[2 * p] = x; rr[2 * p + 1] = y;
            }
        }
        __syncthreads();

        // ---- gate math for the CTA's 4 columns ----
        float hn = 0.f;
        if (tid < 128) {
            float gh0 = 0.f, gh1 = 0.f, gh2 = 0.f;
            if (s > 0) {
                #pragma unroll
                for (int ww = 0; ww < 32; ww++) {
                    const float* rr = red + (ww * 32 + bb) * 13;
                    gh0 += rr[jl];
                    gh1 += rr[4 + jl];
                    gh2 += rr[8 + jl];
                }
            }
            float r = 1.f / (1.f + expf(-(giv0 + gh0 + bh[jl])));
            float z = 1.f / (1.f + expf(-(giv1 + gh1 + bh[4 + jl])));
            float nn = tanhf(giv2 + r * (gh2 + bh[8 + jl]));
            hn = (1.f - z) * nn + z * ho;
            ho = hn;
            g_hT2[(s & 1) * (Hn * Bn) + jg * 32 + bb] = hn;
        }
        __syncthreads();

        // ---- publish progress: ONE release store, no atomics ----
        if (tid == 0) st_rel(&flg[cta * 32], (unsigned)(s + 1));

        // ---- off-critical-path work: states write + next gi prefetch ----
        if (tid < 128) {
            size_t oidx = lay1 ? ((size_t)bb * 128 + s) * 512 + jg
                               : ((size_t)s * 32 + bb) * 512 + jg;
            st_out[oidx] = hn;
            if (s < 127) {
                size_t gib = ((size_t)(s + 1) * 32 + bb) * (size_t)G3;
                giv0 = __ldg(gi + gib + jg);
                giv1 = __ldg(gi + gib + 512 + jg);
                giv2 = __ldg(gi + gib + 1024 + jg);
            }
        }
    }
}

// ======== final: time-attention + linear + softmax ==========================
// states layout here: [b][s][h] (written directly by layer-1 GRU into d_out)
__global__ __launch_bounds__(256)
void final_kernel(const float* __restrict__ states, const float* __restrict__ attw,
                  const float* __restrict__ demoip, const float* __restrict__ linW,
                  const float* __restrict__ linb, float* __restrict__ out) {
    __shared__ float aw[512];
    __shared__ float lg[128];
    __shared__ float al[128];
    __shared__ float ctx[512];
    __shared__ float o10[10];
    const int tid = threadIdx.x, b = blockIdx.x;
    const int w = tid >> 5, lane = tid & 31;
    const float* stb = states + (size_t)b * 128 * 512;

    for (int h = tid; h < 512; h += 256) aw[h] = attw[h];
    __syncthreads();

    for (int s = w; s < 128; s += 8) {
        const float* row = stb + (size_t)s * 512;
        float acc = 0.f;
        for (int h = lane; h < 512; h += 32) acc += row[h] * aw[h];
        acc = wred(acc);
        if (lane == 0) lg[s] = acc;
    }
    __syncthreads();

    if (tid < 32) {
        float v[4]; float m = -1e30f;
        #pragma unroll
        for (int q = 0; q < 4; q++) { v[q] = lg[tid + q * 32]; m = fmaxf(m, v[q]); }
        #pragma unroll
        for (int o = 16; o; o >>= 1) m = fmaxf(m, __shfl_xor_sync(0xffffffffu, m, o));
        float ssum = 0.f;
        #pragma unroll
        for (int q = 0; q < 4; q++) { v[q] = expf(v[q] - m); ssum += v[q]; }
        ssum = wred(ssum);
        #pragma unroll
        for (int q = 0; q < 4; q++) {
            float a = v[q] / ssum;
            al[tid + q * 32] = a;
            out[OFF_AL + b * 128 + tid + q * 32] = a;
        }
    }
    __syncthreads();

    for (int h = tid; h < 512; h += 256) {
        float acc = 0.f;
        for (int s = 0; s < 128; s++) acc += al[s] * stb[(size_t)s * 512 + h];
        ctx[h] = acc;
        out[OFF_CTX + b * 512 + h] = acc;
    }
    __syncthreads();

    if (tid < 10) {
        float acc = linb[tid];
        const float* wrow = linW + tid * 515;
        for (int h = 0; h < 512; h++) acc += ctx[h] * wrow[h];
        for (int d = 0; d < 3; d++) acc += demoip[b * 3 + d] * wrow[512 + d];
        o10[tid] = acc;
    }
    __syncthreads();
    if (tid < 10) {
        float m = -1e30f;
        for (int o = 0; o < 10; o++) m = fmaxf(m, o10[o]);
        float e = expf(o10[tid] - m), ssum = 0.f;
        for (int o = 0; o < 10; o++) ssum += expf(o10[o] - m);
        out[OFF_OUT + b * 10 + tid] = e / ssum;
    }
}

// ======== launch ============================================================
extern "C" void kernel_launch(void* const* d_in, const int* in_sizes, int n_in,
                              void* d_out, int out_size) {
    // batch_size may or may not be materialized as input[2] (size-1 scalar).
    int sh = (in_sizes[2] == 1) ? 1 : 0;

    const float* inp   = (const float*)d_in[0];
    const float* demo  = (const float*)d_in[1];
    const float* convw = (const float*)d_in[2 + sh];
    // conv_b at [3+sh] cancels in the softmax; unused.
    const float* embW  = (const float*)d_in[4 + sh];
    const float* Wi0   = (const float*)d_in[5 + sh];
    const float* Wh0   = (const float*)d_in[6 + sh];
    const float* bi0   = (const float*)d_in[7 + sh];
    const float* bh0   = (const float*)d_in[8 + sh];
    const float* Wi1   = (const float*)d_in[9 + sh];
    const float* Wh1   = (const float*)d_in[10 + sh];
    const float* bi1   = (const float*)d_in[11 + sh];
    const float* bh1   = (const float*)d_in[12 + sh];
    const float* attw  = (const float*)d_in[13 + sh];
    const float* linW  = (const float*)d_in[14 + sh];
    const float* linb  = (const float*)d_in[15 + sh];
    float* out = (float*)d_out;

    cudaFuncSetAttribute(gru_kernel, cudaFuncAttributeMaxDynamicSharedMemorySize, GRU_SMEM);
    cudaFuncSetAttribute(conv_pool_kernel, cudaFuncAttributeMaxDynamicSharedMemorySize, CONV_SMEM);

    void *pc, *pe, *p0, *ps0, *p1;
    cudaGetSymbolAddress(&pc, g_conv);
    cudaGetSymbolAddress(&pe, g_emb);
    cudaGetSymbolAddress(&p0, g_gi0);
    cudaGetSymbolAddress(&ps0, g_st0);
    cudaGetSymbolAddress(&p1, g_gi1);

    conv_pool_kernel<<<Bn * Sn, 256, CONV_SMEM>>>(inp, convw, (float*)pc);

    dim3 ge(In / GBN, (Sn * Bn) / GBM);   // (8, 32)
    dim3 gg(G3 / GBN, (Sn * Bn) / GBM);   // (24, 32)
    gemm_tn<<<ge, 256>>>((const float*)pc, embW, nullptr, (float*)pe, In, 1);
    gemm_tn<<<gg, 256>>>((const float*)pe, Wi0, bi0, (float*)p0, G3, 0);

    gru_kernel<<<128, 1024, GRU_SMEM>>>((const float*)p0, Wh0, bh0, (float*)ps0, 0);

    gemm_tn<<<gg, 256>>>((const float*)ps0, Wi1, bi1, (float*)p1, G3, 0);

    gru_kernel<<<128, 1024, GRU_SMEM>>>((const float*)p1, Wh1, bh1, out + OFF_ST, 1);

    final_kernel<<<Bn, 256>>>(out + OFF_ST, attw, demo, linW, linb, out);
}

// round 17
// speedup vs baseline: 1.0414x; 1.0229x over previous
#include <cuda_runtime.h>
#include <cuda_bf16.h>
#include <cstdint>
#include <cstddef>
#include <math.h>

// Dims
#define Bn 32
#define Sn 128
#define Pn 32
#define In 512
#define Hn 512
#define G3 1536
#define On 10

// Output layout: out[32,10] | states[32,128,512] | context[32,512] | alpha[32,128]
#define OFF_OUT 0
#define OFF_ST  320
#define OFF_CTX 2097472
#define OFF_AL  2113856

// -------- scratch (__device__ globals; no allocations allowed) --------------
__device__ float g_conv[Sn*Bn*In];
__device__ float g_emb [Sn*Bn*In];
__device__ float g_gi0 [Sn*Bn*G3];
__device__ float g_st0 [Sn*Bn*Hn];
__device__ float g_gi1 [Sn*Bn*G3];
__device__ float g_hT2[2*Hn*Bn];     // double-buffered h, transposed [j][b]
// per-CTA step flags, each on its own 128B line. Two arrays (one per layer);
// each layer resets the OTHER layer's array (stream-ordered, race-free).
__device__ __align__(128) unsigned g_flagA[128*32];
__device__ __align__(128) unsigned g_flagB[128*32];

// -------- helpers -----------------------------------------------------------
__device__ __forceinline__ float wred(float v) {
    #pragma unroll
    for (int o = 16; o; o >>= 1) v += __shfl_xor_sync(0xffffffffu, v, o);
    return v;
}
__device__ __forceinline__ unsigned ld_acq(const unsigned* p) {
    unsigned v;
    asm volatile("ld.acquire.gpu.u32 %0,[%1];" : "=r"(v) : "l"(p) : "memory");
    return v;
}
__device__ __forceinline__ void st_rel(unsigned* p, unsigned v) {
    asm volatile("st.release.gpu.u32 [%0],%1;" :: "l"(p), "r"(v) : "memory");
}
__device__ __forceinline__ float ldcg(const float* p) {
    float v;
    asm volatile("ld.global.cg.f32 %0,[%1];" : "=f"(v) : "l"(p));
    return v;
}
__device__ __forceinline__ unsigned tf32r(float v) {
    unsigned r;
    asm("cvt.rna.tf32.f32 %0,%1;" : "=r"(r) : "f"(v));
    return r;
}
#define FMA2(d,a,b) asm("fma.rn.f32x2 %0,%1,%2,%0;" : "+l"(d) : "l"(a), "l"(b))
#define BCAST2(d,f) asm("mov.b64 %0,{%1,%1};" : "=l"(d) : "f"(f))
#define PACK2(d,x,y) asm("mov.b64 %0,{%1,%2};" : "=l"(d) : "f"(x), "f"(y))
#define UNPK2(x,y,d) asm("mov.b64 {%0,%1},%2;" : "=f"(x), "=f"(y) : "l"(d))
#define MMA_TF32(c, a, b0v, b1v) \
    asm volatile("mma.sync.aligned.m16n8k8.row.col.f32.tf32.tf32.f32 " \
        "{%0,%1,%2,%3},{%4,%5,%6,%7},{%8,%9},{%0,%1,%2,%3};" \
        : "+f"((c)[0]), "+f"((c)[1]), "+f"((c)[2]), "+f"((c)[3]) \
        : "r"((a)[0]), "r"((a)[1]), "r"((a)[2]), "r"((a)[3]), \
          "r"(b0v), "r"(b1v))

// ======== K1: conv-attention pooling over P (conv_b cancels in softmax) =====
__global__ __launch_bounds__(256)
void conv_pool_kernel(const float* __restrict__ in, const float* __restrict__ conv_w,
                      float* __restrict__ conv_all) {
    __shared__ float cw[In];
    __shared__ float sc[Pn];
    __shared__ float at[Pn];
    const int tid = threadIdx.x;
    const int bx = blockIdx.x;          // b*S + s
    const int b = bx >> 7, s = bx & 127;
    const float* base = in + (size_t)bx * (Pn * In);

    if (tid < 128) ((float4*)cw)[tid] = ((const float4*)conv_w)[tid];
    __syncthreads();

    const int w = tid >> 5, lane = tid & 31;
    #pragma unroll
    for (int q = 0; q < 4; q++) {
        int p = w * 4 + q;
        const float4* row = (const float4*)(base + (size_t)p * In);
        const float4* cw4 = (const float4*)cw;
        float acc = 0.f;
        for (int kk = lane; kk < 128; kk += 32) {
            float4 x = row[kk], y = cw4[kk];
            acc += x.x*y.x + x.y*y.y + x.z*y.z + x.w*y.w;
        }
        acc = wred(acc);
        if (lane == 0) sc[p] = acc;
    }
    __syncthreads();

    if (tid < 32) {
        float v = sc[tid], m = v;
        #pragma unroll
        for (int o = 16; o; o >>= 1) m = fmaxf(m, __shfl_xor_sync(0xffffffffu, m, o));
        float e = expf(v - m);
        float ssum = wred(e);
        at[tid] = e / ssum;
    }
    __syncthreads();

    float* dst = conv_all + ((size_t)s * Bn + b) * In;   // row = s*32+b
    for (int i = tid; i < In; i += 256) {
        float acc = 0.f;
        #pragma unroll 8
        for (int p = 0; p < Pn; p++) acc += at[p] * base[(size_t)p * In + i];
        dst[i] = acc;
    }
}

// ======== GEMM (3xTF32 tensor-core)  C = act(A[M,512] @ W[N,512]^T + bias) ==
// 128x64 tile, 256 thr (8 warps, 4m x 2n), warp tile 32x32 (2x4 m16n8k8 atoms).
// A,W staged to smem as k-major hi/lo tf32 splits (pad keeps fragment LDS
// conflict-free). C += Ahi*Bhi + Ahi*Blo + Alo*Bhi  (fp32-grade accuracy).
#define GBM 128
#define GBN 64
#define GBK 32
#define APAD 136
#define BPAD 72
__global__ __launch_bounds__(256)
void gemm_tf32(const float* __restrict__ A, const float* __restrict__ W,
               const float* __restrict__ bias, float* __restrict__ C,
               int N, int act) {
    __shared__ float Ah[GBK][APAD];
    __shared__ float Al[GBK][APAD];
    __shared__ float Bh[GBK][BPAD];
    __shared__ float Bl[GBK][BPAD];
    const int tid = threadIdx.x;
    const int row0 = blockIdx.y * GBM;
    const int col0 = blockIdx.x * GBN;
    const int w = tid >> 5, lane = tid & 31;
    const int wm = w >> 1, wn = w & 1;
    const int mbase = wm * 32, nbase = wn * 32;
    const int lq = lane >> 2, lr = lane & 3;     // quad id / in-quad id

    float c[8][4];
    #pragma unroll
    for (int i = 0; i < 8; i++)
        #pragma unroll
        for (int j = 0; j < 4; j++) c[i][j] = 0.f;

    // staging indices: A 4 float4/thread, W 2 float4/thread
    const int am[4] = {tid & 127, (tid + 256) & 127, (tid + 512) & 127, (tid + 768) & 127};
    const int ak[4] = {tid >> 7, (tid + 256) >> 7, (tid + 512) >> 7, (tid + 768) >> 7};
    const int bn_[2] = {tid & 63, (tid + 256) & 63};
    const int bk[2] = {tid >> 6, (tid + 256) >> 6};

    for (int k0 = 0; k0 < 512; k0 += GBK) {
        #pragma unroll
        for (int l = 0; l < 4; l++) {
            float4 v = *(const float4*)(A + (size_t)(row0 + am[l]) * 512 + k0 + ak[l] * 4);
            int m = am[l], kb = ak[l] * 4;
            float e[4] = {v.x, v.y, v.z, v.w};
            #pragma unroll
            for (int j = 0; j < 4; j++) {
                unsigned hi = tf32r(e[j]);
                float hif = __uint_as_float(hi);
                unsigned lo = tf32r(e[j] - hif);
                Ah[kb + j][m] = hif;
                Al[kb + j][m] = __uint_as_float(lo);
            }
        }
        #pragma unroll
        for (int l = 0; l < 2; l++) {
            float4 v = *(const float4*)(W + (size_t)(col0 + bn_[l]) * 512 + k0 + bk[l] * 4);
            int n = bn_[l], kb = bk[l] * 4;
            float e[4] = {v.x, v.y, v.z, v.w};
            #pragma unroll
            for (int j = 0; j < 4; j++) {
                unsigned hi = tf32r(e[j]);
                float hif = __uint_as_float(hi);
                unsigned lo = tf32r(e[j] - hif);
                Bh[kb + j][n] = hif;
                Bl[kb + j][n] = __uint_as_float(lo);
            }
        }
        __syncthreads();

        #pragma unroll
        for (int ks = 0; ks < 4; ks++) {
            const int kk = ks * 8;
            unsigned ah[2][4], al_[2][4];
            #pragma unroll
            for (int ma = 0; ma < 2; ma++) {
                int mr = mbase + ma * 16 + lq;
                ah[ma][0] = __float_as_uint(Ah[kk + lr][mr]);
                ah[ma][1] = __float_as_uint(Ah[kk + lr][mr + 8]);
                ah[ma][2] = __float_as_uint(Ah[kk + lr + 4][mr]);
                ah[ma][3] = __float_as_uint(Ah[kk + lr + 4][mr + 8]);
                al_[ma][0] = __float_as_uint(Al[kk + lr][mr]);
                al_[ma][1] = __float_as_uint(Al[kk + lr][mr + 8]);
                al_[ma][2] = __float_as_uint(Al[kk + lr + 4][mr]);
                al_[ma][3] = __float_as_uint(Al[kk + lr + 4][mr + 8]);
            }
            #pragma unroll
            for (int na = 0; na < 4; na++) {
                int nc = nbase + na * 8 + lq;
                unsigned bh0 = __float_as_uint(Bh[kk + lr][nc]);
                unsigned bh1 = __float_as_uint(Bh[kk + lr + 4][nc]);
                unsigned bl0 = __float_as_uint(Bl[kk + lr][nc]);
                unsigned bl1 = __float_as_uint(Bl[kk + lr + 4][nc]);
                #pragma unroll
                for (int ma = 0; ma < 2; ma++) {
                    MMA_TF32(c[ma * 4 + na], ah[ma], bh0, bh1);
                    MMA_TF32(c[ma * 4 + na], ah[ma], bl0, bl1);
                    MMA_TF32(c[ma * 4 + na], al_[ma], bh0, bh1);
                }
            }
        }
        __syncthreads();
    }

    // epilogue: atom (ma,na): rows mbase+ma*16+lq (+8), cols nbase+na*8+2*lr (+1)
    #pragma unroll
    for (int ma = 0; ma < 2; ma++) {
        #pragma unroll
        for (int na = 0; na < 4; na++) {
            float* cc = c[ma * 4 + na];
            int gr = row0 + mbase + ma * 16 + lq;
            int gc = col0 + nbase + na * 8 + 2 * lr;
            float b0 = bias ? bias[gc] : 0.f;
            float b1 = bias ? bias[gc + 1] : 0.f;
            float v0 = cc[0] + b0, v1 = cc[1] + b1;
            float v2 = cc[2] + b0, v3 = cc[3] + b1;
            if (act == 1) {
                v0 = fminf(1.f, fmaxf(-1.f, v0));
                v1 = fminf(1.f, fmaxf(-1.f, v1));
                v2 = fminf(1.f, fmaxf(-1.f, v2));
                v3 = fminf(1.f, fmaxf(-1.f, v3));
            }
            *(float2*)(C + (size_t)gr * N + gc) = make_float2(v0, v1);
            *(float2*)(C + (size_t)(gr + 8) * N + gc) = make_float2(v2, v3);
        }
    }
}

// ======== GRU persistent recurrence (R12: best measured structure) ==========
// grid=128 CTAs, 1024 thr (32 warps, 8/SMSP for latency hiding).
// CTA c owns h-columns [4c,4c+4) (12 gate cols).
// Warp w: lane=b, 16-k slice k0 = q*128 + (w&7)*16, q=((w>>3)+cta)&3.
// Slice spans 4 producer CTAs -> warp polls 4 per-CTA flags (lane&3).
// h read via ld.global.cg (coherent, MLP=16). Flags: single writer st.release.
#define SM_WP   0
#define SM_RED  32768
#define SM_BH   (32768 + 53248)
#define GRU_SMEM (32768 + 53248 + 64)

__global__ __launch_bounds__(1024)
void gru_kernel(const float* __restrict__ gi, const float* __restrict__ Whh,
                const float* __restrict__ bhh, float* __restrict__ st_out,
                int lay1) {
    extern __shared__ char sm[];
    float* wp  = (float*)(sm + SM_WP);    // [k][16] floats; cols c=0..11 (c=g*4+jl)
    float* red = (float*)(sm + SM_RED);   // [(w*32+b)*13 + c], 32 warps
    float* bh  = (float*)(sm + SM_BH);    // [12]
    const int tid = threadIdx.x;
    const int cta = blockIdx.x;

    unsigned* flg = lay1 ? g_flagB : g_flagA;
    // reset the OTHER layer's flag (only touched by the previous launch)
    if (tid == 0) (lay1 ? g_flagA : g_flagB)[cta * 32] = 0;

    // weights: wp[k*16 + c] = Whh[(g*512 + cta*4 + jl)*512 + k], c = g*4+jl
    for (int i = tid; i < 6144; i += 1024) {
        int c = i >> 9, k = i & 511;
        int g = c >> 2, jl = c & 3;
        wp[k * 16 + c] = Whh[(size_t)(g * 512 + cta * 4 + jl) * 512 + k];
    }
    if (tid < 12) bh[tid] = bhh[(tid >> 2) * 512 + cta * 4 + (tid & 3)];
    __syncthreads();

    const int lane = tid & 31, w = tid >> 5;
    const int q = ((w >> 3) + cta) & 3;          // chunk this warp consumes
    const int k0 = q * 128 + (w & 7) * 16;       // warp's 16-k slice
    const int pc0 = k0 >> 2;                     // first producer CTA of slice
    const unsigned* myflag = &flg[(pc0 + (lane & 3)) * 32];
    // gate-phase identity (tid < 128)
    const int bb = tid & 31, jl = (tid >> 5) & 3;
    const int jg = cta * 4 + jl;

    float giv0 = 0.f, giv1 = 0.f, giv2 = 0.f, ho = 0.f;
    if (tid < 128) {
        giv0 = __ldg(gi + (size_t)bb * G3 + jg);
        giv1 = __ldg(gi + (size_t)bb * G3 + 512 + jg);
        giv2 = __ldg(gi + (size_t)bb * G3 + 1024 + jg);
    }

    for (int s = 0; s < 128; s++) {
        if (s > 0) {
            // ---- warp-autonomous wait for THIS slice's 4 producers ----
            {
                unsigned tgt = (unsigned)s;
                while (!__all_sync(0xffffffffu, ld_acq(myflag) >= tgt)) { }
            }

            // ---- direct L2 read (cg): all 16 h loads in flight at once ----
            const float* hb = g_hT2 + ((s + 1) & 1) * (Hn * Bn) + (size_t)k0 * 32 + lane;
            float hr[16];
            #pragma unroll
            for (int i = 0; i < 16; i++) hr[i] = ldcg(hb + i * 32);

            unsigned long long acc[6];
            #pragma unroll
            for (int p = 0; p < 6; p++) acc[p] = 0ULL;
            #pragma unroll
            for (int i = 0; i < 16; i++) {
                unsigned long long h2;
                BCAST2(h2, hr[i]);
                const ulonglong2* wk = (const ulonglong2*)(wp + (k0 + i) * 16);
                ulonglong2 A = wk[0], Bv = wk[1], Cv = wk[2];
                FMA2(acc[0], h2, A.x);  FMA2(acc[1], h2, A.y);
                FMA2(acc[2], h2, Bv.x); FMA2(acc[3], h2, Bv.y);
                FMA2(acc[4], h2, Cv.x); FMA2(acc[5], h2, Cv.y);
            }
            float* rr = red + (w * 32 + lane) * 13;
            #pragma unroll
            for (int p = 0; p < 6; p++) {
                float x, y;
                UNPK2(x, y, acc[p]);
                rr[2 * p] = x; rr[2 * p + 1] = y;
            }
        }
        __syncthreads();

        // ---- gate math for the CTA's 4 columns ----
        float hn = 0.f;
        if (tid < 128) {
            float gh0 = 0.f, gh1 = 0.f, gh2 = 0.f;
            if (s > 0) {
                #pragma unroll
                for (int ww = 0; ww < 32; ww++) {
                    const float* rr = red + (ww * 32 + bb) * 13;
                    gh0 += rr[jl];
                    gh1 += rr[4 + jl];
                    gh2 += rr[8 + jl];
                }
            }
            float r = 1.f / (1.f + expf(-(giv0 + gh0 + bh[jl])));
            float z = 1.f / (1.f + expf(-(giv1 + gh1 + bh[4 + jl])));
            float nn = tanhf(giv2 + r * (gh2 + bh[8 + jl]));
            hn = (1.f - z) * nn + z * ho;
            ho = hn;
            g_hT2[(s & 1) * (Hn * Bn) + jg * 32 + bb] = hn;
        }
        __syncthreads();

        // ---- publish progress: ONE release store, no atomics ----
        if (tid == 0) st_rel(&flg[cta * 32], (unsigned)(s + 1));

        // ---- off-critical-path work: states write + next gi prefetch ----
        if (tid < 128) {
            size_t oidx = lay1 ? ((size_t)bb * 128 + s) * 512 + jg
                               : ((size_t)s * 32 + bb) * 512 + jg;
            st_out[oidx] = hn;
            if (s < 127) {
                size_t gib = ((size_t)(s + 1) * 32 + bb) * (size_t)G3;
                giv0 = __ldg(gi + gib + jg);
                giv1 = __ldg(gi + gib + 512 + jg);
                giv2 = __ldg(gi + gib + 1024 + jg);
            }
        }
    }
}

// ======== final: time-attention + linear + softmax ==========================
// states layout here: [b][s][h] (written directly by layer-1 GRU into d_out)
__global__ __launch_bounds__(256)
void final_kernel(const float* __restrict__ states, const float* __restrict__ attw,
                  const float* __restrict__ demoip, const float* __restrict__ linW,
                  const float* __restrict__ linb, float* __restrict__ out) {
    __shared__ float aw[512];
    __shared__ float lg[128];
    __shared__ float al[128];
    __shared__ float ctx[512];
    __shared__ float o10[10];
    const int tid = threadIdx.x, b = blockIdx.x;
    const int w = tid >> 5, lane = tid & 31;
    const float* stb = states + (size_t)b * 128 * 512;

    for (int h = tid; h < 512; h += 256) aw[h] = attw[h];
    __syncthreads();

    for (int s = w; s < 128; s += 8) {
        const float* row = stb + (size_t)s * 512;
        float acc = 0.f;
        for (int h = lane; h < 512; h += 32) acc += row[h] * aw[h];
        acc = wred(acc);
        if (lane == 0) lg[s] = acc;
    }
    __syncthreads();

    if (tid < 32) {
        float v[4]; float m = -1e30f;
        #pragma unroll
        for (int q = 0; q < 4; q++) { v[q] = lg[tid + q * 32]; m = fmaxf(m, v[q]); }
        #pragma unroll
        for (int o = 16; o; o >>= 1) m = fmaxf(m, __shfl_xor_sync(0xffffffffu, m, o));
        float ssum = 0.f;
        #pragma unroll
        for (int q = 0; q < 4; q++) { v[q] = expf(v[q] - m); ssum += v[q]; }
        ssum = wred(ssum);
        #pragma unroll
        for (int q = 0; q < 4; q++) {
            float a = v[q] / ssum;
            al[tid + q * 32] = a;
            out[OFF_AL + b * 128 + tid + q * 32] = a;
        }
    }
    __syncthreads();

    for (int h = tid; h < 512; h += 256) {
        float acc = 0.f;
        for (int s = 0; s < 128; s++) acc += al[s] * stb[(size_t)s * 512 + h];
        ctx[h] = acc;
        out[OFF_CTX + b * 512 + h] = acc;
    }
    __syncthreads();

    if (tid < 10) {
        float acc = linb[tid];
        const float* wrow = linW + tid * 515;
        for (int h = 0; h < 512; h++) acc += ctx[h] * wrow[h];
        for (int d = 0; d < 3; d++) acc += demoip[b * 3 + d] * wrow[512 + d];
        o10[tid] = acc;
    }
    __syncthreads();
    if (tid < 10) {
        float m = -1e30f;
        for (int o = 0; o < 10; o++) m = fmaxf(m, o10[o]);
        float e = expf(o10[tid] - m), ssum = 0.f;
        for (int o = 0; o < 10; o++) ssum += expf(o10[o] - m);
        out[OFF_OUT + b * 10 + tid] = e / ssum;
    }
}

// ======== launch ============================================================
extern "C" void kernel_launch(void* const* d_in, const int* in_sizes, int n_in,
                              void* d_out, int out_size) {
    // batch_size may or may not be materialized as input[2] (size-1 scalar).
    int sh = (in_sizes[2] == 1) ? 1 : 0;

    const float* inp   = (const float*)d_in[0];
    const float* demo  = (const float*)d_in[1];
    const float* convw = (const float*)d_in[2 + sh];
    // conv_b at [3+sh] cancels in the softmax; unused.
    const float* embW  = (const float*)d_in[4 + sh];
    const float* Wi0   = (const float*)d_in[5 + sh];
    const float* Wh0   = (const float*)d_in[6 + sh];
    const float* bi0   = (const float*)d_in[7 + sh];
    const float* bh0   = (const float*)d_in[8 + sh];
    const float* Wi1   = (const float*)d_in[9 + sh];
    const float* Wh1   = (const float*)d_in[10 + sh];
    const float* bi1   = (const float*)d_in[11 + sh];
    const float* bh1   = (const float*)d_in[12 + sh];
    const float* attw  = (const float*)d_in[13 + sh];
    const float* linW  = (const float*)d_in[14 + sh];
    const float* linb  = (const float*)d_in[15 + sh];
    float* out = (float*)d_out;

    cudaFuncSetAttribute(gru_kernel, cudaFuncAttributeMaxDynamicSharedMemorySize, GRU_SMEM);

    void *pc, *pe, *p0, *ps0, *p1;
    cudaGetSymbolAddress(&pc, g_conv);
    cudaGetSymbolAddress(&pe, g_emb);
    cudaGetSymbolAddress(&p0, g_gi0);
    cudaGetSymbolAddress(&ps0, g_st0);
    cudaGetSymbolAddress(&p1, g_gi1);

    conv_pool_kernel<<<Bn * Sn, 256>>>(inp, convw, (float*)pc);

    dim3 ge(In / GBN, (Sn * Bn) / GBM);   // (8, 32)
    dim3 gg(G3 / GBN, (Sn * Bn) / GBM);   // (24, 32)
    gemm_tf32<<<ge, 256>>>((const float*)pc, embW, nullptr, (float*)pe, In, 1);
    gemm_tf32<<<gg, 256>>>((const float*)pe, Wi0, bi0, (float*)p0, G3, 0);

    gru_kernel<<<128, 1024, GRU_SMEM>>>((const float*)p0, Wh0, bh0, (float*)ps0, 0);

    gemm_tf32<<<gg, 256>>>((const float*)ps0, Wi1, bi1, (float*)p1, G3, 0);

    gru_kernel<<<128, 1024, GRU_SMEM>>>((const float*)p1, Wh1, bh1, out + OFF_ST, 1);

    final_kernel<<<Bn, 256>>>(out + OFF_ST, attw, demo, linW, linb, out);
}